// round 16
// baseline (speedup 1.0000x reference)
#include <cuda_runtime.h>
#include <cuda_fp16.h>
#include <cstdint>
#include <math.h>

// Problem constants
#define BATCH 2
#define SEQ   2048
#define DM    1024
#define NH    16
#define HD    64
#define FF    4096
#define MROWS (BATCH * SEQ)   // 4096

#define TILE_ELEMS 8192                 // 128 rows x 64 fp16 (SW128)
#define TILE_BYTES 16384
#define STAGE_BYTES 32768               // A tile + B tile
#define NSTAGE 3
#define GEMM_SMEM   (NSTAGE * STAGE_BYTES + 256)
#define ATTN_SMEM   (16384 + 2 * 16384) // Q + 2 KV stages

// ---------------- scratch -----------------------------------------------
__device__ float g_y  [MROWS * DM];

__device__ __half t_xr [MROWS * DM];
__device__ __half t_xn [MROWS * DM];
__device__ __half t_q  [MROWS * DM];
__device__ __half t_k  [MROWS * DM];
__device__ __half t_v  [MROWS * DM];
__device__ __half t_ctx[MROWS * DM];
__device__ __half t_yn [MROWS * DM];
__device__ __half t_h  [MROWS * FF];
__device__ __half t_wqkv[3072 * DM];    // Wq|Wk|Wv tile-contiguous
__device__ __half t_wo [DM * DM];
__device__ __half t_w1 [FF * DM];
__device__ __half t_w2 [DM * FF];

// ---------------- helpers -----------------------------------------------
__device__ __forceinline__ uint32_t sw128(uint32_t o) { return o ^ ((o >> 3) & 0x70); }

__device__ __forceinline__ float fexp(float x)
{
    x = fminf(fmaxf(x, -87.f), 87.f);
    float y = x * 1.4426950408889634f;
    float r = rintf(y);
    float f = y - r;
    float p = 1.33336498e-3f;
    p = fmaf(p, f, 9.61793571e-3f);
    p = fmaf(p, f, 5.55043442e-2f);
    p = fmaf(p, f, 2.40226507e-1f);
    p = fmaf(p, f, 6.93147182e-1f);
    p = fmaf(p, f, 1.0f);
    return p * __int_as_float(((int)r + 127) << 23);
}

__device__ __forceinline__ uint32_t smem_u32(const void* p)
{
    uint32_t a;
    asm("{ .reg .u64 t; cvta.to.shared.u64 t, %1; cvt.u32.u64 %0, t; }" : "=r"(a) : "l"(p));
    return a;
}

__device__ __forceinline__ void cp16(uint32_t s, const void* g)
{
    asm volatile("cp.async.cg.shared.global [%0], [%1], 16;" :: "r"(s), "l"(g));
}

__device__ __forceinline__ void ldsm4(uint32_t* r, uint32_t addr)
{
    asm volatile("ldmatrix.sync.aligned.m8n8.x4.shared.b16 {%0,%1,%2,%3}, [%4];"
                 : "=r"(r[0]), "=r"(r[1]), "=r"(r[2]), "=r"(r[3]) : "r"(addr));
}

__device__ __forceinline__ void ldsm4t(uint32_t* r, uint32_t addr)
{
    asm volatile("ldmatrix.sync.aligned.m8n8.x4.trans.shared.b16 {%0,%1,%2,%3}, [%4];"
                 : "=r"(r[0]), "=r"(r[1]), "=r"(r[2]), "=r"(r[3]) : "r"(addr));
}

__device__ __forceinline__ void mma_f16(float* d, const uint32_t* a, const uint32_t* b)
{
    asm volatile(
        "mma.sync.aligned.m16n8k16.row.col.f32.f16.f16.f32 "
        "{%0,%1,%2,%3}, {%4,%5,%6,%7}, {%8,%9}, {%0,%1,%2,%3};"
        : "+f"(d[0]), "+f"(d[1]), "+f"(d[2]), "+f"(d[3])
        : "r"(a[0]), "r"(a[1]), "r"(a[2]), "r"(a[3]), "r"(b[0]), "r"(b[1]));
}

__device__ __forceinline__ uint32_t pack_h2(float x, float y)
{
    __half2 t = __floats2half2_rn(x, y);
    return *(uint32_t*)&t;
}

// ---------------- RMSNorm (+ optional RoPE) -> tiled fp16 ----------------
__global__ void __launch_bounds__(256) rms_rope_kernel(
    const float* __restrict__ x, const float* __restrict__ scale,
    __half* __restrict__ n_out, __half* __restrict__ r_out)
{
    const int row = blockIdx.x;
    const int tid = threadIdx.x;
    __shared__ float red[8];
    __shared__ float th[32];

    if (r_out != nullptr && tid < 32)
        th[tid] = exp2f((float)tid * (-13.287712379549449f / 32.0f));

    float4 v = *(const float4*)(x + (size_t)row * DM + tid * 4);
    float ss = v.x * v.x + v.y * v.y + v.z * v.z + v.w * v.w;
    #pragma unroll
    for (int o = 16; o > 0; o >>= 1) ss += __shfl_xor_sync(0xffffffffu, ss, o);
    if ((tid & 31) == 0) red[tid >> 5] = ss;
    __syncthreads();
    float tot = 0.f;
    #pragma unroll
    for (int i = 0; i < 8; i++) tot += red[i];
    const float r = rsqrtf(tot * (1.0f / (float)DM) + 1e-6f);

    float4 sc = *(const float4*)(scale + tid * 4);
    float4 n;
    n.x = v.x * r * sc.x;
    n.y = v.y * r * sc.y;
    n.z = v.z * r * sc.z;
    n.w = v.w * r * sc.w;

    const int mt = row >> 7, rr = row & 127;
    const int c0 = tid * 4;
    const int kc = c0 >> 6, kk = c0 & 63;
    const size_t base = ((size_t)mt * (DM / 64) + kc) * TILE_ELEMS;
    const uint32_t off = sw128(rr * 128 + kk * 2) >> 1;
    {
        uint2 pk;
        pk.x = pack_h2(n.x, n.y);
        pk.y = pack_h2(n.z, n.w);
        *(uint2*)(n_out + base + off) = pk;
    }

    if (r_out != nullptr) {
        const int t = row & (SEQ - 1);
        const int c = c0 & (HD - 1);
        const int p = c >> 1;
        float a0 = (float)t * th[p];
        float a1 = (float)t * th[p + 1];
        float s0, co0, s1, co1;
        sincosf(a0, &s0, &co0);
        sincosf(a1, &s1, &co1);
        uint2 pk;
        pk.x = pack_h2(n.x * co0 - n.y * s0, n.y * co0 + n.x * s0);
        pk.y = pack_h2(n.z * co1 - n.w * s1, n.w * co1 + n.z * s1);
        *(uint2*)(r_out + base + off) = pk;
    }
}

// ---------------- fp32 [N,K] -> tiled fp16 (vectorized) ------------------
__global__ void __launch_bounds__(256) conv_tiled_kernel(
    const float* __restrict__ in, int K, __half* __restrict__ out)
{
    const int kc = blockIdx.x;
    const int rt = blockIdx.y;
    const int NCk = gridDim.x;
    const size_t base = ((size_t)rt * NCk + kc) * (size_t)TILE_ELEMS;
    #pragma unroll
    for (int idx = threadIdx.x; idx < 1024; idx += 256) {
        const int r = idx >> 3, k = (idx & 7) * 8;
        const float* gp = in + (size_t)(rt * 128 + r) * K + kc * 64 + k;
        const float4 a = *(const float4*)gp;
        const float4 b = *(const float4*)(gp + 4);
        uint4 pk;
        pk.x = pack_h2(a.x, a.y);
        pk.y = pack_h2(a.z, a.w);
        pk.z = pack_h2(b.x, b.y);
        pk.w = pack_h2(b.z, b.w);
        const uint32_t off = sw128(r * 128 + k * 2) >> 1;
        *(uint4*)(out + base + off) = pk;
    }
}

// ---------------- mma.sync fp16 GEMM: 128 thr, 4 warps, 64x64 warp tile --
// CTA tile stays 128x128; grids unchanged vs R8/R15. ldsm traffic -33%.
// OUTT: 0 = fp32 C (+res), 1 = fp16 tiled O, 2 = split n<1024->O else O2
template <int ACT, int RES, int OUTT>
__global__ void __launch_bounds__(128, 2) gemm_mma(
    const __half* __restrict__ A, const __half* __restrict__ B,
    const float* __restrict__ bias, const float* __restrict__ resid,
    float* __restrict__ C, __half* __restrict__ O, __half* __restrict__ O2,
    int N, int K)
{
    extern __shared__ char smem[];
    const uint32_t sbase = (smem_u32(smem) + 127) & ~127u;

    const int tid = threadIdx.x;
    const int lane = tid & 31, wid = tid >> 5;
    const int wm = wid >> 1, wn = wid & 1;      // 2M x 2N warp grid
    const int NC = K >> 6;
    const int mt = blockIdx.y, nt = blockIdx.x;

    const uint32_t xr = (uint32_t)((lane & 7) << 4);
    uint32_t aRow[4];
    #pragma unroll
    for (int mi = 0; mi < 4; mi++)
        aRow[mi] = (uint32_t)((wm * 64 + mi * 16 + (lane & 15)) * 128);
    const uint32_t kA = (uint32_t)((lane >> 4) * 16);

    const int nb = wn * 64 + ((lane >> 4) << 3) + (lane & 7);
    uint32_t bRow[4];
    #pragma unroll
    for (int np = 0; np < 4; np++)
        bRow[np] = (uint32_t)((nb + np * 16) * 128);
    const uint32_t kB = (uint32_t)(((lane >> 3) & 1) * 16);

    float acc[4][8][4];
    #pragma unroll
    for (int mi = 0; mi < 4; mi++)
        #pragma unroll
        for (int nj = 0; nj < 8; nj++)
            #pragma unroll
            for (int q = 0; q < 4; q++) acc[mi][nj][q] = 0.f;

    auto load_chunk = [&](int i) {
        const uint32_t st = sbase + (uint32_t)(i % NSTAGE) * STAGE_BYTES;
        const char* ga = (const char*)(A + ((size_t)mt * NC + i) * TILE_ELEMS);
        const char* gb = (const char*)(B + ((size_t)nt * NC + i) * TILE_ELEMS);
        #pragma unroll 8
        for (int j = tid; j < 1024; j += 128) {
            cp16(st + j * 16,         ga + j * 16);
            cp16(st + 16384 + j * 16, gb + j * 16);
        }
        asm volatile("cp.async.commit_group;" ::: "memory");
    };

    load_chunk(0);
    if (NC > 1) load_chunk(1);
    for (int i = 0; i < NC; i++) {
        if (i + 2 < NC) {
            load_chunk(i + 2);
            asm volatile("cp.async.wait_group 2;" ::: "memory");
        } else if (i + 1 < NC) {
            asm volatile("cp.async.wait_group 1;" ::: "memory");
        } else {
            asm volatile("cp.async.wait_group 0;" ::: "memory");
        }
        __syncthreads();

        const uint32_t st = sbase + (uint32_t)(i % NSTAGE) * STAGE_BYTES;
        const uint32_t sA = st, sB = st + 16384;

        #pragma unroll
        for (int ks = 0; ks < 4; ks++) {
            const uint32_t ka = (uint32_t)(ks * 32) + kA;
            const uint32_t kb = (uint32_t)(ks * 32) + kB;
            uint32_t a[4][4], b[4][4];
            #pragma unroll
            for (int mi = 0; mi < 4; mi++)
                ldsm4(a[mi], sA + aRow[mi] + (ka ^ xr));
            #pragma unroll
            for (int np = 0; np < 4; np++)
                ldsm4(b[np], sB + bRow[np] + (kb ^ xr));
            #pragma unroll
            for (int mi = 0; mi < 4; mi++)
                #pragma unroll
                for (int nj = 0; nj < 8; nj++)
                    mma_f16(acc[mi][nj], a[mi], &b[nj >> 1][(nj & 1) * 2]);
        }
        __syncthreads();
    }

    const int m_base = mt * 128 + wm * 64 + (lane >> 2);
    const int n_base = nt * 128 + wn * 64 + (lane & 3) * 2;
    #pragma unroll
    for (int mi = 0; mi < 4; mi++) {
        #pragma unroll
        for (int nj = 0; nj < 8; nj++) {
            const int n = n_base + nj * 8;
            const float b0 = bias[n], b1 = bias[n + 1];
            float v00 = acc[mi][nj][0] + b0, v01 = acc[mi][nj][1] + b1;
            float v10 = acc[mi][nj][2] + b0, v11 = acc[mi][nj][3] + b1;
            if (ACT == 1) {
                v00 = v00 / (1.0f + fexp(-v00));
                v01 = v01 / (1.0f + fexp(-v01));
                v10 = v10 / (1.0f + fexp(-v10));
                v11 = v11 / (1.0f + fexp(-v11));
            }
            const int m0 = m_base + mi * 16, m1 = m0 + 8;
            if (OUTT >= 1) {
                int kc = n >> 6;
                __half* Od = O;
                int ntiles = N >> 6;
                if (OUTT == 2) {
                    ntiles = 16;
                    if (kc >= 16) { Od = O2; kc -= 16; }
                }
                const int kk = n & 63;
                const size_t tb = ((size_t)mt * ntiles + kc) * TILE_ELEMS;
                const uint32_t o0 = sw128((m0 & 127) * 128 + kk * 2) >> 1;
                const uint32_t o1 = sw128((m1 & 127) * 128 + kk * 2) >> 1;
                *(uint32_t*)(Od + tb + o0) = pack_h2(v00, v01);
                *(uint32_t*)(Od + tb + o1) = pack_h2(v10, v11);
            } else {
                const size_t o0 = (size_t)m0 * N + n;
                const size_t o1 = (size_t)m1 * N + n;
                if (RES == 1) {
                    float2 r0 = *(const float2*)(resid + o0);
                    float2 r1 = *(const float2*)(resid + o1);
                    v00 += r0.x; v01 += r0.y; v10 += r1.x; v11 += r1.y;
                }
                *(float2*)(C + o0) = make_float2(v00, v01);
                *(float2*)(C + o1) = make_float2(v10, v11);
            }
        }
    }
}

// ---------------- tensor-core causal flash attention (paired q-tiles) ----
// grid (8, 16 heads, 2 batch); each CTA handles q-tiles {15-bx, bx}
__global__ void __launch_bounds__(256, 2) flash_mma_kernel(
    const __half* __restrict__ Q, const __half* __restrict__ K,
    const __half* __restrict__ V, __half* __restrict__ Cc)
{
    extern __shared__ char smem[];
    const uint32_t sbase = smem_u32(smem);

    const int tid = threadIdx.x, lane = tid & 31, wq = tid >> 5;
    const int h = blockIdx.y, b = blockIdx.z;

    const uint32_t xr = (uint32_t)((lane & 7) << 4);
    const uint32_t aRow = (uint32_t)((wq * 16 + (lane & 15)) * 128);
    const uint32_t kA = (uint32_t)((lane >> 4) * 16);
    const uint32_t nbK = (uint32_t)(((lane >> 4) << 3) + (lane & 7));
    const uint32_t kB = (uint32_t)(((lane >> 3) & 1) * 16);
    const int vmi = lane >> 3, vri = lane & 7;
    const uint32_t sQ = sbase;

    #pragma unroll
    for (int sel = 0; sel < 2; sel++) {
        const int qt = (sel == 0) ? (15 - blockIdx.x) : blockIdx.x;  // big first
        const int mtq = b * 16 + qt;
        const int KT = 2 * qt + 2;

        // Q tile async load
        {
            const char* gQ = (const char*)(Q + ((size_t)mtq * 16 + h) * TILE_ELEMS);
            for (int j = tid; j < 1024; j += 256)
                cp16(sQ + j * 16, gQ + j * 16);
            asm volatile("cp.async.commit_group;" ::: "memory");
        }

        auto load_kv = [&](int kt) {
            const uint32_t st = sbase + 16384 + (uint32_t)(kt & 1) * 16384;
            const int mtk = b * 16 + (kt >> 1);
            const size_t toff = ((size_t)mtk * 16 + h) * TILE_ELEMS + (size_t)(kt & 1) * 4096;
            const char* gk = (const char*)(K + toff);
            const char* gv = (const char*)(V + toff);
            for (int j = tid; j < 512; j += 256) {
                cp16(st + j * 16,        gk + j * 16);
                cp16(st + 8192 + j * 16, gv + j * 16);
            }
            asm volatile("cp.async.commit_group;" ::: "memory");
        };
        load_kv(0);
        asm volatile("cp.async.wait_group 0;" ::: "memory");
        __syncthreads();

        uint32_t qf[4][4];
        #pragma unroll
        for (int ks = 0; ks < 4; ks++)
            ldsm4(qf[ks], sQ + aRow + (((uint32_t)(ks * 32) + kA) ^ xr));

        float o[8][4];
        #pragma unroll
        for (int nj = 0; nj < 8; nj++)
            #pragma unroll
            for (int q = 0; q < 4; q++) o[nj][q] = 0.f;
        float m0 = -1e30f, m1 = -1e30f, l0 = 0.f, l1 = 0.f;

        const int row_lo = qt * 128 + wq * 16;

        for (int kt = 0; kt < KT; kt++) {
            if (kt + 1 < KT) {
                load_kv(kt + 1);
                asm volatile("cp.async.wait_group 1;" ::: "memory");
            } else {
                asm volatile("cp.async.wait_group 0;" ::: "memory");
            }
            __syncthreads();

            if (kt * 64 <= row_lo + 15) {
                const uint32_t st = sbase + 16384 + (uint32_t)(kt & 1) * 16384;
                const uint32_t sK = st, sV = st + 8192;

                float S[8][4];
                #pragma unroll
                for (int nj = 0; nj < 8; nj++)
                    #pragma unroll
                    for (int q = 0; q < 4; q++) S[nj][q] = 0.f;

                #pragma unroll
                for (int ks = 0; ks < 4; ks++) {
                    const uint32_t kb = (uint32_t)(ks * 32) + kB;
                    uint32_t bk[4][4];
                    #pragma unroll
                    for (int np = 0; np < 4; np++)
                        ldsm4(bk[np], sK + (nbK + np * 16) * 128 + (kb ^ xr));
                    #pragma unroll
                    for (int nj = 0; nj < 8; nj++)
                        mma_f16(S[nj], qf[ks], &bk[nj >> 1][(nj & 1) * 2]);
                }

                const int r0 = row_lo + (lane >> 2);
                const bool need_mask = (kt * 64 + 63) > row_lo;
                #pragma unroll
                for (int nj = 0; nj < 8; nj++)
                    #pragma unroll
                    for (int q = 0; q < 4; q++) S[nj][q] *= 0.125f;
                if (need_mask) {
                    #pragma unroll
                    for (int nj = 0; nj < 8; nj++)
                        #pragma unroll
                        for (int q = 0; q < 4; q++) {
                            const int kg = kt * 64 + nj * 8 + (lane & 3) * 2 + (q & 1);
                            const int qg = r0 + ((q >= 2) ? 8 : 0);
                            if (kg > qg) S[nj][q] = -1e30f;
                        }
                }

                float t0 = -1e30f, t1 = -1e30f;
                #pragma unroll
                for (int nj = 0; nj < 8; nj++) {
                    t0 = fmaxf(t0, fmaxf(S[nj][0], S[nj][1]));
                    t1 = fmaxf(t1, fmaxf(S[nj][2], S[nj][3]));
                }
                t0 = fmaxf(t0, __shfl_xor_sync(0xffffffffu, t0, 1));
                t0 = fmaxf(t0, __shfl_xor_sync(0xffffffffu, t0, 2));
                t1 = fmaxf(t1, __shfl_xor_sync(0xffffffffu, t1, 1));
                t1 = fmaxf(t1, __shfl_xor_sync(0xffffffffu, t1, 2));
                const float mn0 = fmaxf(m0, t0), mn1 = fmaxf(m1, t1);
                const float c0 = fexp(m0 - mn0), c1 = fexp(m1 - mn1);
                m0 = mn0; m1 = mn1;
                l0 *= c0; l1 *= c1;
                #pragma unroll
                for (int nj = 0; nj < 8; nj++) {
                    o[nj][0] *= c0; o[nj][1] *= c0;
                    o[nj][2] *= c1; o[nj][3] *= c1;
                }
                float ls0 = 0.f, ls1 = 0.f;
                #pragma unroll
                for (int nj = 0; nj < 8; nj++) {
                    S[nj][0] = fexp(S[nj][0] - mn0); ls0 += S[nj][0];
                    S[nj][1] = fexp(S[nj][1] - mn0); ls0 += S[nj][1];
                    S[nj][2] = fexp(S[nj][2] - mn1); ls1 += S[nj][2];
                    S[nj][3] = fexp(S[nj][3] - mn1); ls1 += S[nj][3];
                }
                l0 += ls0; l1 += ls1;

                #pragma unroll
                for (int kk = 0; kk < 4; kk++) {
                    uint32_t ap[4];
                    ap[0] = pack_h2(S[2*kk][0],   S[2*kk][1]);
                    ap[1] = pack_h2(S[2*kk][2],   S[2*kk][3]);
                    ap[2] = pack_h2(S[2*kk+1][0], S[2*kk+1][1]);
                    ap[3] = pack_h2(S[2*kk+1][2], S[2*kk+1][3]);
                    uint32_t vf[4][4];
                    const uint32_t vrow = (uint32_t)(kk * 16 + (vmi & 1) * 8 + vri);
                    #pragma unroll
                    for (int g = 0; g < 4; g++) {
                        const uint32_t off = sw128(vrow * 128 + (uint32_t)(g * 16 + (vmi >> 1) * 8) * 2);
                        ldsm4t(vf[g], sV + off);
                    }
                    #pragma unroll
                    for (int nj = 0; nj < 8; nj++)
                        mma_f16(o[nj], ap, &vf[nj >> 1][(nj & 1) * 2]);
                }
            }
            __syncthreads();
        }

        l0 += __shfl_xor_sync(0xffffffffu, l0, 1);
        l0 += __shfl_xor_sync(0xffffffffu, l0, 2);
        l1 += __shfl_xor_sync(0xffffffffu, l1, 1);
        l1 += __shfl_xor_sync(0xffffffffu, l1, 2);
        const float inv0 = 1.0f / l0, inv1 = 1.0f / l1;

        const size_t tb = ((size_t)mtq * 16 + h) * TILE_ELEMS;
        const int rl0 = wq * 16 + (lane >> 2), rl1 = rl0 + 8;
        #pragma unroll
        for (int nj = 0; nj < 8; nj++) {
            const int col = nj * 8 + (lane & 3) * 2;
            const uint32_t o0 = sw128(rl0 * 128 + col * 2) >> 1;
            const uint32_t o1 = sw128(rl1 * 128 + col * 2) >> 1;
            *(uint32_t*)(Cc + tb + o0) = pack_h2(o[nj][0] * inv0, o[nj][1] * inv0);
            *(uint32_t*)(Cc + tb + o1) = pack_h2(o[nj][2] * inv1, o[nj][3] * inv1);
        }
        __syncthreads();   // all warps done with KV buffers before next tile's loads
    }
}

// ---------------- launch -------------------------------------------------
#define SYMADDR(p, s) cudaGetSymbolAddress((void**)&(p), s)

extern "C" void kernel_launch(void* const* d_in, const int* in_sizes, int n_in,
                              void* d_out, int out_size)
{
    const float* x         = (const float*)d_in[0];
    const float* rms_scale = (const float*)d_in[1];
    const float* in_proj_w = (const float*)d_in[2];
    const float* in_proj_b = (const float*)d_in[3];
    const float* out_proj_w= (const float*)d_in[4];
    const float* out_proj_b= (const float*)d_in[5];
    const float* w1        = (const float*)d_in[6];
    const float* b1        = (const float*)d_in[7];
    const float* w2        = (const float*)d_in[8];
    const float* b2        = (const float*)d_in[9];
    float* out = (float*)d_out;

    float *p_y;
    __half *xr, *xn, *q, *k, *v, *ctx, *yn, *hh;
    __half *wqkv, *wo, *w1h, *w2h;
    SYMADDR(p_y, g_y);
    SYMADDR(xr, t_xr);   SYMADDR(xn, t_xn);
    SYMADDR(q, t_q);     SYMADDR(k, t_k);    SYMADDR(v, t_v);
    SYMADDR(ctx, t_ctx); SYMADDR(yn, t_yn);  SYMADDR(hh, t_h);
    SYMADDR(wqkv, t_wqkv); SYMADDR(wo, t_wo);
    SYMADDR(w1h, t_w1);  SYMADDR(w2h, t_w2);
    __half* wv = wqkv + (size_t)2048 * DM;

    static bool inited = false;
    static cudaStream_t s2, s3;
    static cudaEvent_t evRoot, evW, evKW, evA, evV;
    if (!inited) {
        cudaStreamCreateWithFlags(&s2, cudaStreamNonBlocking);
        cudaStreamCreateWithFlags(&s3, cudaStreamNonBlocking);
        cudaEventCreateWithFlags(&evRoot, cudaEventDisableTiming);
        cudaEventCreateWithFlags(&evW,    cudaEventDisableTiming);
        cudaEventCreateWithFlags(&evKW,   cudaEventDisableTiming);
        cudaEventCreateWithFlags(&evA,    cudaEventDisableTiming);
        cudaEventCreateWithFlags(&evV,    cudaEventDisableTiming);
        cudaFuncSetAttribute(gemm_mma<0,0,0>, cudaFuncAttributeMaxDynamicSharedMemorySize, GEMM_SMEM);
        cudaFuncSetAttribute(gemm_mma<0,0,1>, cudaFuncAttributeMaxDynamicSharedMemorySize, GEMM_SMEM);
        cudaFuncSetAttribute(gemm_mma<0,0,2>, cudaFuncAttributeMaxDynamicSharedMemorySize, GEMM_SMEM);
        cudaFuncSetAttribute(gemm_mma<1,0,1>, cudaFuncAttributeMaxDynamicSharedMemorySize, GEMM_SMEM);
        cudaFuncSetAttribute(gemm_mma<0,1,0>, cudaFuncAttributeMaxDynamicSharedMemorySize, GEMM_SMEM);
        cudaFuncSetAttribute(flash_mma_kernel, cudaFuncAttributeMaxDynamicSharedMemorySize, ATTN_SMEM);
        inited = true;
    }

    // fork point
    cudaEventRecord(evRoot, 0);
    cudaStreamWaitEvent(s2, evRoot, 0);
    cudaStreamWaitEvent(s3, evRoot, 0);

    // s2: weight conversions not needed until step 4+
    conv_tiled_kernel<<<dim3(16, 8),  256, 0, s2>>>(out_proj_w, DM, wo);
    conv_tiled_kernel<<<dim3(16, 32), 256, 0, s2>>>(w1,         DM, w1h);
    conv_tiled_kernel<<<dim3(64, 8),  256, 0, s2>>>(w2,         FF, w2h);
    cudaEventRecord(evW, s2);

    // s3: qkv weight conversion, parallel to rms_rope
    conv_tiled_kernel<<<dim3(16, 24), 256, 0, s3>>>(in_proj_w, DM, wqkv);
    cudaEventRecord(evKW, s3);

    // main: xn = rmsnorm(x); xr = rope(xn)
    rms_rope_kernel<<<MROWS, 256>>>(x, rms_scale, xn, xr);
    cudaEventRecord(evA, 0);

    // s3: v = xn @ Wv^T  (after rms_rope; parallel to QK GEMM on main)
    cudaStreamWaitEvent(s3, evA, 0);
    gemm_mma<0,0,1><<<dim3(8, 32), 128, GEMM_SMEM, s3>>>(
        xn, wv, in_proj_b + 2 * DM, nullptr, nullptr, v, nullptr, DM, DM);
    cudaEventRecord(evV, s3);

    // main: [q|k] = xr @ [Wq;Wk]^T + b (needs wqkv conversion)
    cudaStreamWaitEvent(0, evKW, 0);
    gemm_mma<0,0,2><<<dim3(16, 32), 128, GEMM_SMEM>>>(
        xr, wqkv, in_proj_b, nullptr, nullptr, q, k, 2 * DM, DM);

    // join: attention needs q,k (main) and v (s3)
    cudaStreamWaitEvent(0, evV, 0);
    flash_mma_kernel<<<dim3(8, NH, BATCH), 256, ATTN_SMEM>>>(q, k, v, ctx);

    // join: Wo/W1/W2 conversions
    cudaStreamWaitEvent(0, evW, 0);

    // y = ctx @ Wo^T + b
    gemm_mma<0,0,0><<<dim3(8, 32), 128, GEMM_SMEM>>>(
        ctx, wo, out_proj_b, nullptr, p_y, nullptr, nullptr, DM, DM);

    // yn = rmsnorm(y)
    rms_rope_kernel<<<MROWS, 256>>>(p_y, rms_scale, yn, nullptr);

    // h = silu(yn @ w1^T + b1) -> tiled fp16
    gemm_mma<1,0,1><<<dim3(32, 32), 128, GEMM_SMEM>>>(
        yn, w1h, b1, nullptr, nullptr, hh, nullptr, FF, DM);

    // out = y + (h @ w2^T + b2)
    gemm_mma<0,1,0><<<dim3(8, 32), 128, GEMM_SMEM>>>(
        hh, w2h, b2, p_y, out, nullptr, nullptr, DM, FF);
}

// round 17
// speedup vs baseline: 1.0045x; 1.0045x over previous
#include <cuda_runtime.h>
#include <cuda_fp16.h>
#include <cstdint>
#include <math.h>

// Problem constants
#define BATCH 2
#define SEQ   2048
#define DM    1024
#define NH    16
#define HD    64
#define FF    4096
#define MROWS (BATCH * SEQ)   // 4096

#define TILE_ELEMS 8192                 // 128 rows x 64 fp16 (SW128)
#define TILE_BYTES 16384
#define STAGE_BYTES 32768               // A tile + B tile
#define NSTAGE 3
#define GEMM_SMEM   (NSTAGE * STAGE_BYTES + 256)
#define ATTN_SMEM   (16384 + 2 * 16384) // Q + 2 KV stages

// ---------------- scratch -----------------------------------------------
__device__ float g_y  [MROWS * DM];

__device__ __half t_xr [MROWS * DM];
__device__ __half t_xn [MROWS * DM];
__device__ __half t_q  [MROWS * DM];
__device__ __half t_k  [MROWS * DM];
__device__ __half t_v  [MROWS * DM];
__device__ __half t_ctx[MROWS * DM];
__device__ __half t_yn [MROWS * DM];
__device__ __half t_h  [MROWS * FF];
__device__ __half t_wqkv[3072 * DM];    // Wq|Wk|Wv tile-contiguous
__device__ __half t_wo [DM * DM];
__device__ __half t_w1 [FF * DM];
__device__ __half t_w2 [DM * FF];

// ---------------- helpers -----------------------------------------------
__device__ __forceinline__ uint32_t sw128(uint32_t o) { return o ^ ((o >> 3) & 0x70); }

__device__ __forceinline__ float fexp(float x)
{
    x = fminf(fmaxf(x, -87.f), 87.f);
    float y = x * 1.4426950408889634f;
    float r = rintf(y);
    float f = y - r;
    float p = 1.33336498e-3f;
    p = fmaf(p, f, 9.61793571e-3f);
    p = fmaf(p, f, 5.55043442e-2f);
    p = fmaf(p, f, 2.40226507e-1f);
    p = fmaf(p, f, 6.93147182e-1f);
    p = fmaf(p, f, 1.0f);
    return p * __int_as_float(((int)r + 127) << 23);
}

__device__ __forceinline__ uint32_t smem_u32(const void* p)
{
    uint32_t a;
    asm("{ .reg .u64 t; cvta.to.shared.u64 t, %1; cvt.u32.u64 %0, t; }" : "=r"(a) : "l"(p));
    return a;
}

__device__ __forceinline__ void cp16(uint32_t s, const void* g)
{
    asm volatile("cp.async.cg.shared.global [%0], [%1], 16;" :: "r"(s), "l"(g));
}

__device__ __forceinline__ void ldsm4(uint32_t* r, uint32_t addr)
{
    asm volatile("ldmatrix.sync.aligned.m8n8.x4.shared.b16 {%0,%1,%2,%3}, [%4];"
                 : "=r"(r[0]), "=r"(r[1]), "=r"(r[2]), "=r"(r[3]) : "r"(addr));
}

__device__ __forceinline__ void ldsm4t(uint32_t* r, uint32_t addr)
{
    asm volatile("ldmatrix.sync.aligned.m8n8.x4.trans.shared.b16 {%0,%1,%2,%3}, [%4];"
                 : "=r"(r[0]), "=r"(r[1]), "=r"(r[2]), "=r"(r[3]) : "r"(addr));
}

__device__ __forceinline__ void mma_f16(float* d, const uint32_t* a, const uint32_t* b)
{
    asm volatile(
        "mma.sync.aligned.m16n8k16.row.col.f32.f16.f16.f32 "
        "{%0,%1,%2,%3}, {%4,%5,%6,%7}, {%8,%9}, {%0,%1,%2,%3};"
        : "+f"(d[0]), "+f"(d[1]), "+f"(d[2]), "+f"(d[3])
        : "r"(a[0]), "r"(a[1]), "r"(a[2]), "r"(a[3]), "r"(b[0]), "r"(b[1]));
}

__device__ __forceinline__ uint32_t pack_h2(float x, float y)
{
    __half2 t = __floats2half2_rn(x, y);
    return *(uint32_t*)&t;
}

// ---------------- RMSNorm (+ optional RoPE) -> tiled fp16 ----------------
__global__ void __launch_bounds__(256) rms_rope_kernel(
    const float* __restrict__ x, const float* __restrict__ scale,
    __half* __restrict__ n_out, __half* __restrict__ r_out)
{
    const int row = blockIdx.x;
    const int tid = threadIdx.x;
    __shared__ float red[8];
    __shared__ float th[32];

    if (r_out != nullptr && tid < 32)
        th[tid] = exp2f((float)tid * (-13.287712379549449f / 32.0f));

    float4 v = *(const float4*)(x + (size_t)row * DM + tid * 4);
    float ss = v.x * v.x + v.y * v.y + v.z * v.z + v.w * v.w;
    #pragma unroll
    for (int o = 16; o > 0; o >>= 1) ss += __shfl_xor_sync(0xffffffffu, ss, o);
    if ((tid & 31) == 0) red[tid >> 5] = ss;
    __syncthreads();
    float tot = 0.f;
    #pragma unroll
    for (int i = 0; i < 8; i++) tot += red[i];
    const float r = rsqrtf(tot * (1.0f / (float)DM) + 1e-6f);

    float4 sc = *(const float4*)(scale + tid * 4);
    float4 n;
    n.x = v.x * r * sc.x;
    n.y = v.y * r * sc.y;
    n.z = v.z * r * sc.z;
    n.w = v.w * r * sc.w;

    const int mt = row >> 7, rr = row & 127;
    const int c0 = tid * 4;
    const int kc = c0 >> 6, kk = c0 & 63;
    const size_t base = ((size_t)mt * (DM / 64) + kc) * TILE_ELEMS;
    const uint32_t off = sw128(rr * 128 + kk * 2) >> 1;
    {
        uint2 pk;
        pk.x = pack_h2(n.x, n.y);
        pk.y = pack_h2(n.z, n.w);
        *(uint2*)(n_out + base + off) = pk;
    }

    if (r_out != nullptr) {
        const int t = row & (SEQ - 1);
        const int c = c0 & (HD - 1);
        const int p = c >> 1;
        float a0 = (float)t * th[p];
        float a1 = (float)t * th[p + 1];
        float s0, co0, s1, co1;
        sincosf(a0, &s0, &co0);
        sincosf(a1, &s1, &co1);
        uint2 pk;
        pk.x = pack_h2(n.x * co0 - n.y * s0, n.y * co0 + n.x * s0);
        pk.y = pack_h2(n.z * co1 - n.w * s1, n.w * co1 + n.z * s1);
        *(uint2*)(r_out + base + off) = pk;
    }
}

// ---------------- fp32 [N,K] -> tiled fp16 (vectorized) ------------------
__global__ void __launch_bounds__(256) conv_tiled_kernel(
    const float* __restrict__ in, int K, __half* __restrict__ out)
{
    const int kc = blockIdx.x;
    const int rt = blockIdx.y;
    const int NCk = gridDim.x;
    const size_t base = ((size_t)rt * NCk + kc) * (size_t)TILE_ELEMS;
    #pragma unroll
    for (int idx = threadIdx.x; idx < 1024; idx += 256) {
        const int r = idx >> 3, k = (idx & 7) * 8;
        const float* gp = in + (size_t)(rt * 128 + r) * K + kc * 64 + k;
        const float4 a = *(const float4*)gp;
        const float4 b = *(const float4*)(gp + 4);
        uint4 pk;
        pk.x = pack_h2(a.x, a.y);
        pk.y = pack_h2(a.z, a.w);
        pk.z = pack_h2(b.x, b.y);
        pk.w = pack_h2(b.z, b.w);
        const uint32_t off = sw128(r * 128 + k * 2) >> 1;
        *(uint4*)(out + base + off) = pk;
    }
}

// ---------------- mma.sync fp16 GEMM (3-stage pipeline, R8 optimum) ------
// OUTT: 0 = fp32 row-major C (optional residual), 1 = fp16 tiled O,
//       2 = fp16 tiled split: n<1024 -> O, n>=1024 -> O2
template <int ACT, int RES, int OUTT>
__global__ void __launch_bounds__(256, 2) gemm_mma(
    const __half* __restrict__ A, const __half* __restrict__ B,
    const float* __restrict__ bias, const float* __restrict__ resid,
    float* __restrict__ C, __half* __restrict__ O, __half* __restrict__ O2,
    int N, int K)
{
    extern __shared__ char smem[];
    const uint32_t sbase = (smem_u32(smem) + 127) & ~127u;

    const int tid = threadIdx.x;
    const int lane = tid & 31, wid = tid >> 5;
    const int wm = wid >> 1, wn = wid & 1;
    const int NC = K >> 6;
    const int mt = blockIdx.y, nt = blockIdx.x;

    const uint32_t xr = (uint32_t)((lane & 7) << 4);
    uint32_t aRow[2];
    #pragma unroll
    for (int mi = 0; mi < 2; mi++)
        aRow[mi] = (uint32_t)((wm * 32 + mi * 16 + (lane & 15)) * 128);
    const uint32_t kA = (uint32_t)((lane >> 4) * 16);

    const int nb = wn * 64 + ((lane >> 4) << 3) + (lane & 7);
    uint32_t bRow[4];
    #pragma unroll
    for (int np = 0; np < 4; np++)
        bRow[np] = (uint32_t)((nb + np * 16) * 128);
    const uint32_t kB = (uint32_t)(((lane >> 3) & 1) * 16);

    float acc[2][8][4];
    #pragma unroll
    for (int mi = 0; mi < 2; mi++)
        #pragma unroll
        for (int nj = 0; nj < 8; nj++)
            #pragma unroll
            for (int q = 0; q < 4; q++) acc[mi][nj][q] = 0.f;

    auto load_chunk = [&](int i) {
        const uint32_t st = sbase + (uint32_t)(i % NSTAGE) * STAGE_BYTES;
        const char* ga = (const char*)(A + ((size_t)mt * NC + i) * TILE_ELEMS);
        const char* gb = (const char*)(B + ((size_t)nt * NC + i) * TILE_ELEMS);
        #pragma unroll 4
        for (int j = tid; j < 1024; j += 256) {
            cp16(st + j * 16,         ga + j * 16);
            cp16(st + 16384 + j * 16, gb + j * 16);
        }
        asm volatile("cp.async.commit_group;" ::: "memory");
    };

    load_chunk(0);
    if (NC > 1) load_chunk(1);
    for (int i = 0; i < NC; i++) {
        if (i + 2 < NC) {
            load_chunk(i + 2);
            asm volatile("cp.async.wait_group 2;" ::: "memory");
        } else if (i + 1 < NC) {
            asm volatile("cp.async.wait_group 1;" ::: "memory");
        } else {
            asm volatile("cp.async.wait_group 0;" ::: "memory");
        }
        __syncthreads();

        const uint32_t st = sbase + (uint32_t)(i % NSTAGE) * STAGE_BYTES;
        const uint32_t sA = st, sB = st + 16384;

        #pragma unroll
        for (int ks = 0; ks < 4; ks++) {
            const uint32_t ka = (uint32_t)(ks * 32) + kA;
            const uint32_t kb = (uint32_t)(ks * 32) + kB;
            uint32_t a[2][4], b[4][4];
            #pragma unroll
            for (int mi = 0; mi < 2; mi++)
                ldsm4(a[mi], sA + aRow[mi] + (ka ^ xr));
            #pragma unroll
            for (int np = 0; np < 4; np++)
                ldsm4(b[np], sB + bRow[np] + (kb ^ xr));
            #pragma unroll
            for (int mi = 0; mi < 2; mi++)
                #pragma unroll
                for (int nj = 0; nj < 8; nj++)
                    mma_f16(acc[mi][nj], a[mi], &b[nj >> 1][(nj & 1) * 2]);
        }
        __syncthreads();
    }

    const int m_base = mt * 128 + wm * 32 + (lane >> 2);
    const int n_base = nt * 128 + wn * 64 + (lane & 3) * 2;
    #pragma unroll
    for (int mi = 0; mi < 2; mi++) {
        #pragma unroll
        for (int nj = 0; nj < 8; nj++) {
            const int n = n_base + nj * 8;
            const float b0 = bias[n], b1 = bias[n + 1];
            float v00 = acc[mi][nj][0] + b0, v01 = acc[mi][nj][1] + b1;
            float v10 = acc[mi][nj][2] + b0, v11 = acc[mi][nj][3] + b1;
            if (ACT == 1) {
                v00 = v00 / (1.0f + fexp(-v00));
                v01 = v01 / (1.0f + fexp(-v01));
                v10 = v10 / (1.0f + fexp(-v10));
                v11 = v11 / (1.0f + fexp(-v11));
            }
            const int m0 = m_base + mi * 16, m1 = m0 + 8;
            if (OUTT >= 1) {
                int kc = n >> 6;
                __half* Od = O;
                int ntiles = N >> 6;
                if (OUTT == 2) {
                    ntiles = 16;
                    if (kc >= 16) { Od = O2; kc -= 16; }
                }
                const int kk = n & 63;
                const size_t tb = ((size_t)mt * ntiles + kc) * TILE_ELEMS;
                const uint32_t o0 = sw128((m0 & 127) * 128 + kk * 2) >> 1;
                const uint32_t o1 = sw128((m1 & 127) * 128 + kk * 2) >> 1;
                *(uint32_t*)(Od + tb + o0) = pack_h2(v00, v01);
                *(uint32_t*)(Od + tb + o1) = pack_h2(v10, v11);
            } else {
                const size_t o0 = (size_t)m0 * N + n;
                const size_t o1 = (size_t)m1 * N + n;
                if (RES == 1) {
                    float2 r0 = *(const float2*)(resid + o0);
                    float2 r1 = *(const float2*)(resid + o1);
                    v00 += r0.x; v01 += r0.y; v10 += r1.x; v11 += r1.y;
                }
                *(float2*)(C + o0) = make_float2(v00, v01);
                *(float2*)(C + o1) = make_float2(v10, v11);
            }
        }
    }
}

// ---------------- tensor-core causal flash attention (paired q-tiles) ----
// grid (8, 16 heads, 2 batch); each CTA handles q-tiles {15-bx, bx}
// -> uniform 34 KV-chunks per CTA, 256 CTAs = single wave at 2 CTA/SM.
__global__ void __launch_bounds__(256, 2) flash_mma_kernel(
    const __half* __restrict__ Q, const __half* __restrict__ K,
    const __half* __restrict__ V, __half* __restrict__ Cc)
{
    extern __shared__ char smem[];
    const uint32_t sbase = smem_u32(smem);

    const int tid = threadIdx.x, lane = tid & 31, wq = tid >> 5;
    const int h = blockIdx.y, b = blockIdx.z;

    const uint32_t xr = (uint32_t)((lane & 7) << 4);
    const uint32_t aRow = (uint32_t)((wq * 16 + (lane & 15)) * 128);
    const uint32_t kA = (uint32_t)((lane >> 4) * 16);
    const uint32_t nbK = (uint32_t)(((lane >> 4) << 3) + (lane & 7));
    const uint32_t kB = (uint32_t)(((lane >> 3) & 1) * 16);
    const int vmi = lane >> 3, vri = lane & 7;
    const uint32_t sQ = sbase;

    #pragma unroll
    for (int sel = 0; sel < 2; sel++) {
        const int qt = (sel == 0) ? (15 - blockIdx.x) : blockIdx.x;  // big first
        const int mtq = b * 16 + qt;
        const int KT = 2 * qt + 2;

        // Q tile async load
        {
            const char* gQ = (const char*)(Q + ((size_t)mtq * 16 + h) * TILE_ELEMS);
            for (int j = tid; j < 1024; j += 256)
                cp16(sQ + j * 16, gQ + j * 16);
            asm volatile("cp.async.commit_group;" ::: "memory");
        }

        auto load_kv = [&](int kt) {
            const uint32_t st = sbase + 16384 + (uint32_t)(kt & 1) * 16384;
            const int mtk = b * 16 + (kt >> 1);
            const size_t toff = ((size_t)mtk * 16 + h) * TILE_ELEMS + (size_t)(kt & 1) * 4096;
            const char* gk = (const char*)(K + toff);
            const char* gv = (const char*)(V + toff);
            for (int j = tid; j < 512; j += 256) {
                cp16(st + j * 16,        gk + j * 16);
                cp16(st + 8192 + j * 16, gv + j * 16);
            }
            asm volatile("cp.async.commit_group;" ::: "memory");
        };
        load_kv(0);
        asm volatile("cp.async.wait_group 0;" ::: "memory");
        __syncthreads();

        uint32_t qf[4][4];
        #pragma unroll
        for (int ks = 0; ks < 4; ks++)
            ldsm4(qf[ks], sQ + aRow + (((uint32_t)(ks * 32) + kA) ^ xr));

        float o[8][4];
        #pragma unroll
        for (int nj = 0; nj < 8; nj++)
            #pragma unroll
            for (int q = 0; q < 4; q++) o[nj][q] = 0.f;
        float m0 = -1e30f, m1 = -1e30f, l0 = 0.f, l1 = 0.f;

        const int row_lo = qt * 128 + wq * 16;

        for (int kt = 0; kt < KT; kt++) {
            if (kt + 1 < KT) {
                load_kv(kt + 1);
                asm volatile("cp.async.wait_group 1;" ::: "memory");
            } else {
                asm volatile("cp.async.wait_group 0;" ::: "memory");
            }
            __syncthreads();

            if (kt * 64 <= row_lo + 15) {
                const uint32_t st = sbase + 16384 + (uint32_t)(kt & 1) * 16384;
                const uint32_t sK = st, sV = st + 8192;

                float S[8][4];
                #pragma unroll
                for (int nj = 0; nj < 8; nj++)
                    #pragma unroll
                    for (int q = 0; q < 4; q++) S[nj][q] = 0.f;

                #pragma unroll
                for (int ks = 0; ks < 4; ks++) {
                    const uint32_t kb = (uint32_t)(ks * 32) + kB;
                    uint32_t bk[4][4];
                    #pragma unroll
                    for (int np = 0; np < 4; np++)
                        ldsm4(bk[np], sK + (nbK + np * 16) * 128 + (kb ^ xr));
                    #pragma unroll
                    for (int nj = 0; nj < 8; nj++)
                        mma_f16(S[nj], qf[ks], &bk[nj >> 1][(nj & 1) * 2]);
                }

                const int r0 = row_lo + (lane >> 2);
                const bool need_mask = (kt * 64 + 63) > row_lo;
                #pragma unroll
                for (int nj = 0; nj < 8; nj++)
                    #pragma unroll
                    for (int q = 0; q < 4; q++) S[nj][q] *= 0.125f;
                if (need_mask) {
                    #pragma unroll
                    for (int nj = 0; nj < 8; nj++)
                        #pragma unroll
                        for (int q = 0; q < 4; q++) {
                            const int kg = kt * 64 + nj * 8 + (lane & 3) * 2 + (q & 1);
                            const int qg = r0 + ((q >= 2) ? 8 : 0);
                            if (kg > qg) S[nj][q] = -1e30f;
                        }
                }

                float t0 = -1e30f, t1 = -1e30f;
                #pragma unroll
                for (int nj = 0; nj < 8; nj++) {
                    t0 = fmaxf(t0, fmaxf(S[nj][0], S[nj][1]));
                    t1 = fmaxf(t1, fmaxf(S[nj][2], S[nj][3]));
                }
                t0 = fmaxf(t0, __shfl_xor_sync(0xffffffffu, t0, 1));
                t0 = fmaxf(t0, __shfl_xor_sync(0xffffffffu, t0, 2));
                t1 = fmaxf(t1, __shfl_xor_sync(0xffffffffu, t1, 1));
                t1 = fmaxf(t1, __shfl_xor_sync(0xffffffffu, t1, 2));
                const float mn0 = fmaxf(m0, t0), mn1 = fmaxf(m1, t1);
                const float c0 = fexp(m0 - mn0), c1 = fexp(m1 - mn1);
                m0 = mn0; m1 = mn1;
                l0 *= c0; l1 *= c1;
                #pragma unroll
                for (int nj = 0; nj < 8; nj++) {
                    o[nj][0] *= c0; o[nj][1] *= c0;
                    o[nj][2] *= c1; o[nj][3] *= c1;
                }
                float ls0 = 0.f, ls1 = 0.f;
                #pragma unroll
                for (int nj = 0; nj < 8; nj++) {
                    S[nj][0] = fexp(S[nj][0] - mn0); ls0 += S[nj][0];
                    S[nj][1] = fexp(S[nj][1] - mn0); ls0 += S[nj][1];
                    S[nj][2] = fexp(S[nj][2] - mn1); ls1 += S[nj][2];
                    S[nj][3] = fexp(S[nj][3] - mn1); ls1 += S[nj][3];
                }
                l0 += ls0; l1 += ls1;

                #pragma unroll
                for (int kk = 0; kk < 4; kk++) {
                    uint32_t ap[4];
                    ap[0] = pack_h2(S[2*kk][0],   S[2*kk][1]);
                    ap[1] = pack_h2(S[2*kk][2],   S[2*kk][3]);
                    ap[2] = pack_h2(S[2*kk+1][0], S[2*kk+1][1]);
                    ap[3] = pack_h2(S[2*kk+1][2], S[2*kk+1][3]);
                    uint32_t vf[4][4];
                    const uint32_t vrow = (uint32_t)(kk * 16 + (vmi & 1) * 8 + vri);
                    #pragma unroll
                    for (int g = 0; g < 4; g++) {
                        const uint32_t off = sw128(vrow * 128 + (uint32_t)(g * 16 + (vmi >> 1) * 8) * 2);
                        ldsm4t(vf[g], sV + off);
                    }
                    #pragma unroll
                    for (int nj = 0; nj < 8; nj++)
                        mma_f16(o[nj], ap, &vf[nj >> 1][(nj & 1) * 2]);
                }
            }
            __syncthreads();
        }

        l0 += __shfl_xor_sync(0xffffffffu, l0, 1);
        l0 += __shfl_xor_sync(0xffffffffu, l0, 2);
        l1 += __shfl_xor_sync(0xffffffffu, l1, 1);
        l1 += __shfl_xor_sync(0xffffffffu, l1, 2);
        const float inv0 = 1.0f / l0, inv1 = 1.0f / l1;

        const size_t tb = ((size_t)mtq * 16 + h) * TILE_ELEMS;
        const int rl0 = wq * 16 + (lane >> 2), rl1 = rl0 + 8;
        #pragma unroll
        for (int nj = 0; nj < 8; nj++) {
            const int col = nj * 8 + (lane & 3) * 2;
            const uint32_t o0 = sw128(rl0 * 128 + col * 2) >> 1;
            const uint32_t o1 = sw128(rl1 * 128 + col * 2) >> 1;
            *(uint32_t*)(Cc + tb + o0) = pack_h2(o[nj][0] * inv0, o[nj][1] * inv0);
            *(uint32_t*)(Cc + tb + o1) = pack_h2(o[nj][2] * inv1, o[nj][3] * inv1);
        }
        __syncthreads();   // all warps done with KV buffers before next tile's loads
    }
}

// ---------------- launch -------------------------------------------------
#define SYMADDR(p, s) cudaGetSymbolAddress((void**)&(p), s)

extern "C" void kernel_launch(void* const* d_in, const int* in_sizes, int n_in,
                              void* d_out, int out_size)
{
    const float* x         = (const float*)d_in[0];
    const float* rms_scale = (const float*)d_in[1];
    const float* in_proj_w = (const float*)d_in[2];
    const float* in_proj_b = (const float*)d_in[3];
    const float* out_proj_w= (const float*)d_in[4];
    const float* out_proj_b= (const float*)d_in[5];
    const float* w1        = (const float*)d_in[6];
    const float* b1        = (const float*)d_in[7];
    const float* w2        = (const float*)d_in[8];
    const float* b2        = (const float*)d_in[9];
    float* out = (float*)d_out;

    float *p_y;
    __half *xr, *xn, *q, *k, *v, *ctx, *yn, *hh;
    __half *wqkv, *wo, *w1h, *w2h;
    SYMADDR(p_y, g_y);
    SYMADDR(xr, t_xr);   SYMADDR(xn, t_xn);
    SYMADDR(q, t_q);     SYMADDR(k, t_k);    SYMADDR(v, t_v);
    SYMADDR(ctx, t_ctx); SYMADDR(yn, t_yn);  SYMADDR(hh, t_h);
    SYMADDR(wqkv, t_wqkv); SYMADDR(wo, t_wo);
    SYMADDR(w1h, t_w1);  SYMADDR(w2h, t_w2);
    __half* wv = wqkv + (size_t)2048 * DM;

    static bool inited = false;
    static cudaStream_t s2, s3;
    static cudaEvent_t evRoot, evW, evKW, evA, evV;
    if (!inited) {
        cudaStreamCreateWithFlags(&s2, cudaStreamNonBlocking);
        cudaStreamCreateWithFlags(&s3, cudaStreamNonBlocking);
        cudaEventCreateWithFlags(&evRoot, cudaEventDisableTiming);
        cudaEventCreateWithFlags(&evW,    cudaEventDisableTiming);
        cudaEventCreateWithFlags(&evKW,   cudaEventDisableTiming);
        cudaEventCreateWithFlags(&evA,    cudaEventDisableTiming);
        cudaEventCreateWithFlags(&evV,    cudaEventDisableTiming);
        cudaFuncSetAttribute(gemm_mma<0,0,0>, cudaFuncAttributeMaxDynamicSharedMemorySize, GEMM_SMEM);
        cudaFuncSetAttribute(gemm_mma<0,0,1>, cudaFuncAttributeMaxDynamicSharedMemorySize, GEMM_SMEM);
        cudaFuncSetAttribute(gemm_mma<0,0,2>, cudaFuncAttributeMaxDynamicSharedMemorySize, GEMM_SMEM);
        cudaFuncSetAttribute(gemm_mma<1,0,1>, cudaFuncAttributeMaxDynamicSharedMemorySize, GEMM_SMEM);
        cudaFuncSetAttribute(gemm_mma<0,1,0>, cudaFuncAttributeMaxDynamicSharedMemorySize, GEMM_SMEM);
        cudaFuncSetAttribute(flash_mma_kernel, cudaFuncAttributeMaxDynamicSharedMemorySize, ATTN_SMEM);
        inited = true;
    }

    // fork point
    cudaEventRecord(evRoot, 0);
    cudaStreamWaitEvent(s2, evRoot, 0);
    cudaStreamWaitEvent(s3, evRoot, 0);

    // s2: weight conversions not needed until step 4+
    conv_tiled_kernel<<<dim3(16, 8),  256, 0, s2>>>(out_proj_w, DM, wo);
    conv_tiled_kernel<<<dim3(16, 32), 256, 0, s2>>>(w1,         DM, w1h);
    conv_tiled_kernel<<<dim3(64, 8),  256, 0, s2>>>(w2,         FF, w2h);
    cudaEventRecord(evW, s2);

    // s3: qkv weight conversion, parallel to rms_rope
    conv_tiled_kernel<<<dim3(16, 24), 256, 0, s3>>>(in_proj_w, DM, wqkv);
    cudaEventRecord(evKW, s3);

    // main: xn = rmsnorm(x); xr = rope(xn)
    rms_rope_kernel<<<MROWS, 256>>>(x, rms_scale, xn, xr);
    cudaEventRecord(evA, 0);

    // s3: v = xn @ Wv^T  (after rms_rope; parallel to QK GEMM on main)
    cudaStreamWaitEvent(s3, evA, 0);
    gemm_mma<0,0,1><<<dim3(8, 32), 256, GEMM_SMEM, s3>>>(
        xn, wv, in_proj_b + 2 * DM, nullptr, nullptr, v, nullptr, DM, DM);
    cudaEventRecord(evV, s3);

    // main: [q|k] = xr @ [Wq;Wk]^T + b (needs wqkv conversion)
    cudaStreamWaitEvent(0, evKW, 0);
    gemm_mma<0,0,2><<<dim3(16, 32), 256, GEMM_SMEM>>>(
        xr, wqkv, in_proj_b, nullptr, nullptr, q, k, 2 * DM, DM);

    // join: attention needs q,k (main) and v (s3)
    cudaStreamWaitEvent(0, evV, 0);
    flash_mma_kernel<<<dim3(8, NH, BATCH), 256, ATTN_SMEM>>>(q, k, v, ctx);

    // join: Wo/W1/W2 conversions
    cudaStreamWaitEvent(0, evW, 0);

    // y = ctx @ Wo^T + b
    gemm_mma<0,0,0><<<dim3(8, 32), 256, GEMM_SMEM>>>(
        ctx, wo, out_proj_b, nullptr, p_y, nullptr, nullptr, DM, DM);

    // yn = rmsnorm(y)
    rms_rope_kernel<<<MROWS, 256>>>(p_y, rms_scale, yn, nullptr);

    // h = silu(yn @ w1^T + b1) -> tiled fp16
    gemm_mma<1,0,1><<<dim3(32, 32), 256, GEMM_SMEM>>>(
        yn, w1h, b1, nullptr, nullptr, hh, nullptr, FF, DM);

    // out = y + (h @ w2^T + b2)
    gemm_mma<0,1,0><<<dim3(8, 32), 256, GEMM_SMEM>>>(
        hh, w2h, b2, p_y, out, nullptr, nullptr, DM, FF);
}